// round 15
// baseline (speedup 1.0000x reference)
#include <cuda_runtime.h>
#include <cuda_fp16.h>
#include <math.h>
#include <stdint.h>

#define MROWS 4096   // B * S
#define DM    1024
#define DH    64
#define NH    16
#define DMLP  4096
#define SEQ   2048
#define BATCH 2

// ---------------- scratch (static device globals; no runtime alloc) ----------
__device__ __half g_xln   [MROWS * DM];
__device__ __half g_qkv   [MROWS * 3 * DM];   // [row][{Q,K,V} x (n*64+h)]
__device__ __half g_ctx   [MROWS * DM];
__device__ float  g_mid   [MROWS * DM];       // fp32: residual carrier
__device__ __half g_y     [MROWS * DM];
__device__ __half g_h     [MROWS * DMLP];
__device__ __half g_wqkv_t[3 * DM * DM];      // [N=3072][K=1024]
__device__ __half g_watt_t[DM * DM];          // [N=1024][K=1024]
__device__ __half g_wmin_t[DMLP * DM];        // [N=4096][K=1024]
__device__ __half g_wmout_t[DM * DMLP];       // [N=1024][K=4096]
__device__ float  g_bqkv  [3 * DM];

// ---------------- helpers ----------------------------------------------------
__device__ __forceinline__ uint32_t smem_u32(const void* p) {
    uint32_t a;
    asm("{ .reg .u64 t; cvta.to.shared.u64 t, %1; cvt.u32.u64 %0, t; }" : "=r"(a) : "l"(p));
    return a;
}
__device__ __forceinline__ void cp_async16(uint32_t s, const void* g) {
    asm volatile("cp.async.cg.shared.global [%0], [%1], 16;" :: "r"(s), "l"(g));
}
#define CP_COMMIT() asm volatile("cp.async.commit_group;")
#define CP_WAIT(n)  asm volatile("cp.async.wait_group %0;" :: "n"(n))

__device__ __forceinline__ void ldm_x4(uint32_t* r, uint32_t addr) {
    asm volatile("ldmatrix.sync.aligned.m8n8.x4.shared.b16 {%0,%1,%2,%3}, [%4];"
        : "=r"(r[0]), "=r"(r[1]), "=r"(r[2]), "=r"(r[3]) : "r"(addr));
}
__device__ __forceinline__ void ldm_x4_trans(uint32_t* r, uint32_t addr) {
    asm volatile("ldmatrix.sync.aligned.m8n8.x4.trans.shared.b16 {%0,%1,%2,%3}, [%4];"
        : "=r"(r[0]), "=r"(r[1]), "=r"(r[2]), "=r"(r[3]) : "r"(addr));
}

// mma.m16n8k16 f16 -> f32
__device__ __forceinline__ void mma16816(float* c, const uint32_t* a,
                                         uint32_t b0, uint32_t b1) {
    asm volatile(
        "mma.sync.aligned.m16n8k16.row.col.f32.f16.f16.f32 "
        "{%0,%1,%2,%3}, {%4,%5,%6,%7}, {%8,%9}, {%0,%1,%2,%3};"
        : "+f"(c[0]), "+f"(c[1]), "+f"(c[2]), "+f"(c[3])
        : "r"(a[0]), "r"(a[1]), "r"(a[2]), "r"(a[3]), "r"(b0), "r"(b1));
}

// ---------------- layernorm: fp32 in -> half out ------------------------------
__global__ __launch_bounds__(256) void ln_kernel(const float* __restrict__ x,
                                                 const float* __restrict__ w,
                                                 const float* __restrict__ bb,
                                                 __half* __restrict__ out)
{
    int row = blockIdx.x;
    int t = threadIdx.x;
    const float* xr = x + (size_t)row * DM;
    float4 xv = reinterpret_cast<const float4*>(xr)[t];
    float s  = xv.x + xv.y + xv.z + xv.w;
    float sq = xv.x*xv.x + xv.y*xv.y + xv.z*xv.z + xv.w*xv.w;
    #pragma unroll
    for (int off = 16; off > 0; off >>= 1) {
        s  += __shfl_xor_sync(0xffffffffu, s,  off);
        sq += __shfl_xor_sync(0xffffffffu, sq, off);
    }
    __shared__ float ss[8], sk[8];
    __shared__ float smean, sinv;
    if ((t & 31) == 0) { ss[t >> 5] = s; sk[t >> 5] = sq; }
    __syncthreads();
    if (t == 0) {
        float S = 0.f, Q = 0.f;
        #pragma unroll
        for (int i = 0; i < 8; i++) { S += ss[i]; Q += sk[i]; }
        float mean = S * (1.0f / DM);
        float var  = Q * (1.0f / DM) - mean * mean;
        smean = mean;
        sinv  = rsqrtf(var + 1e-5f);
    }
    __syncthreads();
    float mean = smean, inv = sinv;
    float4 wv = reinterpret_cast<const float4*>(w)[t];
    float4 bv = reinterpret_cast<const float4*>(bb)[t];
    __half2* o2 = reinterpret_cast<__half2*>(out + (size_t)row * DM);
    o2[2 * t]     = __floats2half2_rn((xv.x - mean) * inv * wv.x + bv.x,
                                      (xv.y - mean) * inv * wv.y + bv.y);
    o2[2 * t + 1] = __floats2half2_rn((xv.z - mean) * inv * wv.z + bv.z,
                                      (xv.w - mean) * inv * wv.w + bv.w);
}

// ---------------- batched weight transposes (to [N][K], half) -----------------
__global__ void transpose3_kernel(const float* __restrict__ Watt,
                                  const float* __restrict__ Wmin,
                                  const float* __restrict__ Wmout)
{
    __shared__ float tile[32][33];
    int bid = blockIdx.x;
    const float* in; __half* out; int R, C, bx, by;
    if (bid < 1024) {                       // W_attn_out [1024][1024]
        in = Watt; out = g_watt_t; R = DM; C = DM;
        bx = bid & 31; by = bid >> 5;
    } else if (bid < 1024 + 4096) {         // W_mlp_in [1024][4096]
        int v = bid - 1024;
        in = Wmin; out = g_wmin_t; R = DM; C = DMLP;
        bx = v & 127; by = v >> 7;
    } else {                                // W_mlp_out [4096][1024]
        int v = bid - 5120;
        in = Wmout; out = g_wmout_t; R = DMLP; C = DM;
        bx = v & 31; by = v >> 5;
    }
    int r0 = by * 32, c0 = bx * 32;
    int tx = threadIdx.x, ty = threadIdx.y;
    #pragma unroll
    for (int i = 0; i < 32; i += 8)
        tile[ty + i][tx] = in[(size_t)(r0 + ty + i) * C + c0 + tx];
    __syncthreads();
    #pragma unroll
    for (int i = 0; i < 32; i += 8)
        out[(size_t)(c0 + ty + i) * R + r0 + tx] = __float2half_rn(tile[tx][ty + i]);
}

// QKV: g_wqkv_t[(sel*1024 + n*64 + h)][e] = W_sel[n][e][h]; query scaled by 1/8
__global__ void qkv_t_kernel(const float* __restrict__ Wq, const float* __restrict__ Wk,
                             const float* __restrict__ Wv)
{
    __shared__ float tile[32][33];
    int b   = blockIdx.z;
    int sel = b >> 4, n = b & 15;
    const float* W = (sel == 0) ? Wq : (sel == 1) ? Wk : Wv;
    float scale = (sel == 0) ? 0.125f : 1.0f;
    const float* src = W + (size_t)n * DM * DH;       // [E=1024][H=64]
    int e0 = blockIdx.x * 32, h0 = blockIdx.y * 32;
    int tx = threadIdx.x, ty = threadIdx.y;
    #pragma unroll
    for (int i = 0; i < 32; i += 8)
        tile[ty + i][tx] = src[(size_t)(e0 + ty + i) * DH + h0 + tx];
    __syncthreads();
    #pragma unroll
    for (int i = 0; i < 32; i += 8)
        g_wqkv_t[(size_t)(sel * DM + n * 64 + h0 + ty + i) * DM + e0 + tx] =
            __float2half_rn(tile[tx][ty + i] * scale);
}

__global__ void bias_pack_kernel(const float* __restrict__ Bq, const float* __restrict__ Bk,
                                 const float* __restrict__ Bv)
{
    int idx = blockIdx.x * 256 + threadIdx.x;
    if (idx < 3 * DM) {
        int sel = idx / DM, col = idx % DM;
        const float* Bp = (sel == 0) ? Bq : (sel == 1) ? Bk : Bv;
        g_bqkv[idx] = Bp[col] * (sel == 0 ? 0.125f : 1.0f);
    }
}

// ---------------- pipelined fp16 mma GEMM: 128x128, 4-stage --------------------
// R13 config + prefetch hoisted to right after the barrier: buffer (c+3)%4 ==
// (c-1)%4 was last read in iter c-1, so the overwrite is race-free and the load
// overlaps the whole tile compute. No occupancy forcing (R14 lesson: reg cap
// spills).
// mode 0: +bias -> half   1: +bias,GELU -> half   2: +bias,+add(f32) -> f32
#define GSTGB 20480   // bytes per stage: 256 rows * 40 halves * 2
#define NSTG  4

__global__ __launch_bounds__(256) void mgemm(
    const __half* __restrict__ A, const __half* __restrict__ Bt,
    void* __restrict__ Cv, int M, int N, int K,
    const float* __restrict__ bias, const float* __restrict__ add, int mode)
{
    extern __shared__ __align__(16) unsigned char smb[];
    uint32_t sb = smem_u32(smb);
    int t    = threadIdx.x;
    int lane = t & 31, wid = t >> 5;
    int g    = lane >> 2, tig = lane & 3;
    int lr   = lane & 7, quad = lane >> 3;
    int wm   = (wid >> 1) * 32;
    int wn   = (wid & 1) * 64;
    int m0   = blockIdx.y * 128, n0 = blockIdx.x * 128;
    int NC   = K >> 5;

    float acc[2][8][4];
    #pragma unroll
    for (int i = 0; i < 2; i++)
        #pragma unroll
        for (int j = 0; j < 8; j++)
            #pragma unroll
            for (int q = 0; q < 4; q++) acc[i][j][q] = 0.f;

    // cp.async slots: 4 x 16B (8 halves) per thread per stage
    uint32_t so[4];
    const __half* gp[4];
    #pragma unroll
    for (int u = 0; u < 4; u++) {
        int idx = u * 256 + t;
        bool isB = idx >= 512;
        int v = idx & 511;
        int r = v >> 2, w = v & 3;
        so[u] = (uint32_t)(((isB ? 5120 : 0) + r * 40 + w * 8) * 2);
        gp[u] = (isB ? Bt + (size_t)(n0 + r) * K : A + (size_t)(m0 + r) * K) + w * 8;
    }

    // prologue: stages 0,1,2
    #pragma unroll
    for (int c = 0; c < 3; c++) {
        uint32_t base = sb + c * GSTGB;
        #pragma unroll
        for (int u = 0; u < 4; u++) cp_async16(base + so[u], gp[u] + c * 32);
        CP_COMMIT();
    }

    // per-lane ldmatrix base offsets (halves)
    int a_row = lr + (quad & 1) * 8, a_kof = (quad >> 1) * 8;       // A-type frag
    int b_row = lr + (quad >> 1) * 8, b_kof = (quad & 1) * 8;       // B-type frag

    for (int c = 0; c < NC; c++) {
        CP_WAIT(2);
        __syncthreads();
        // prefetch c+3 FIRST: overlaps the whole compute below
        if (c + 3 < NC) {
            uint32_t base = sb + ((c + 3) % NSTG) * GSTGB;
            #pragma unroll
            for (int u = 0; u < 4; u++) cp_async16(base + so[u], gp[u] + (c + 3) * 32);
        }
        CP_COMMIT();

        uint32_t stb = sb + (c % NSTG) * GSTGB;
        #pragma unroll
        for (int ko = 0; ko < 32; ko += 16) {   // halves
            uint32_t a[2][4];
            #pragma unroll
            for (int i = 0; i < 2; i++)
                ldm_x4(a[i], stb + (uint32_t)(((wm + i * 16 + a_row) * 40 + ko + a_kof) * 2));
            #pragma unroll
            for (int j2 = 0; j2 < 4; j2++) {
                uint32_t bb[4];
                ldm_x4(bb, stb + (uint32_t)(((128 + wn + j2 * 16 + b_row) * 40 + ko + b_kof) * 2));
                mma16816(acc[0][j2 * 2],     a[0], bb[0], bb[1]);
                mma16816(acc[1][j2 * 2],     a[1], bb[0], bb[1]);
                mma16816(acc[0][j2 * 2 + 1], a[0], bb[2], bb[3]);
                mma16816(acc[1][j2 * 2 + 1], a[1], bb[2], bb[3]);
            }
        }
    }

    // epilogue
    #pragma unroll
    for (int i = 0; i < 2; i++) {
        int r0 = m0 + wm + i * 16 + g;
        int r1 = r0 + 8;
        #pragma unroll
        for (int j = 0; j < 8; j++) {
            int col = n0 + wn + j * 8 + 2 * tig;
            float b0 = bias[col], b1 = bias[col + 1];
            float v0 = acc[i][j][0] + b0, v1 = acc[i][j][1] + b1;
            float v2 = acc[i][j][2] + b0, v3 = acc[i][j][3] + b1;
            if (mode == 1) {
                v0 = 0.5f * v0 * (1.0f + erff(v0 * 0.70710678118654752f));
                v1 = 0.5f * v1 * (1.0f + erff(v1 * 0.70710678118654752f));
                v2 = 0.5f * v2 * (1.0f + erff(v2 * 0.70710678118654752f));
                v3 = 0.5f * v3 * (1.0f + erff(v3 * 0.70710678118654752f));
            }
            if (mode == 2) {
                float* C = (float*)Cv;
                float2 a0 = *reinterpret_cast<const float2*>(add + (size_t)r0 * N + col);
                float2 a1 = *reinterpret_cast<const float2*>(add + (size_t)r1 * N + col);
                *reinterpret_cast<float2*>(C + (size_t)r0 * N + col) = make_float2(v0 + a0.x, v1 + a0.y);
                *reinterpret_cast<float2*>(C + (size_t)r1 * N + col) = make_float2(v2 + a1.x, v3 + a1.y);
            } else {
                __half* C = (__half*)Cv;
                *reinterpret_cast<__half2*>(C + (size_t)r0 * N + col) = __floats2half2_rn(v0, v1);
                *reinterpret_cast<__half2*>(C + (size_t)r1 * N + col) = __floats2half2_rn(v2, v3);
            }
        }
    }
}

// ---------------- fp16 flash attention: QT=128, KT=64, 3-stage KV --------------
// R13 config + prefetch hoisted after the top barrier (dst (c+2)%3 last read in
// iter c-1). No occupancy forcing.
#define KVSTR 72
#define KOFFH(s) (9216 + (s) * 4608)
#define VOFFH(s) (23040 + (s) * 4608)
#define FLASH_SMEM 73728

__global__ __launch_bounds__(256) void flash_mma(const __half* __restrict__ qkv,
                                                 __half* __restrict__ ctx)
{
    extern __shared__ __align__(16) unsigned char smb[];
    uint32_t sb = smem_u32(smb);
    int t    = threadIdx.x;
    int lane = t & 31, wid = t >> 5;
    int g    = lane >> 2, tig = lane & 3;
    int lr   = lane & 7, quad = lane >> 3;
    int n    = blockIdx.y & (NH - 1);
    int b    = blockIdx.y >> 4;
    int q0   = blockIdx.x * 128;
    const __half* base = qkv + (size_t)b * SEQ * (3 * DM);

    // Q tile: 128 rows x 64 halves = 1024 chunks
    #pragma unroll
    for (int u = 0; u < 4; u++) {
        int idx = u * 256 + t;
        int r = idx >> 3, w = idx & 7;
        cp_async16(sb + (uint32_t)((r * KVSTR + w * 8) * 2),
                   base + (size_t)(q0 + r) * (3 * DM) + n * 64 + w * 8);
    }
    CP_COMMIT();
    // KV stages 0,1: 64 rows x 8 chunks each; t<128 K, t>=128 V
    {
        int tt = t & 127;
        #pragma unroll
        for (int s = 0; s < 2; s++) {
            #pragma unroll
            for (int u = 0; u < 4; u++) {
                int idx = u * 128 + tt;
                int r = idx >> 3, w = idx & 7;
                const __half* gsrc = base + (size_t)(s * 64 + r) * (3 * DM) + n * 64 + w * 8;
                if (t < 128)
                    cp_async16(sb + (uint32_t)((KOFFH(s) + r * KVSTR + w * 8) * 2), gsrc + DM);
                else
                    cp_async16(sb + (uint32_t)((VOFFH(s) + r * KVSTR + w * 8) * 2), gsrc + 2 * DM);
            }
            CP_COMMIT();
        }
    }
    CP_WAIT(2);              // Q group complete
    __syncthreads();

    int a_row = lr + (quad & 1) * 8, a_kof = (quad >> 1) * 8;   // A-type frag
    int b_row = lr + (quad >> 1) * 8, b_kof = (quad & 1) * 8;   // B-type frag

    // preload Q frags; Q region becomes P after
    uint32_t qa[4][4];
    #pragma unroll
    for (int ks = 0; ks < 4; ks++)
        ldm_x4(qa[ks], sb + (uint32_t)(((16 * wid + a_row) * KVSTR + ks * 16 + a_kof) * 2));
    uint32_t* Pu = reinterpret_cast<uint32_t*>(smb);   // overlay, stride 36 u32
    int qr = 16 * wid + g;

    float o[8][4];
    #pragma unroll
    for (int j = 0; j < 8; j++)
        #pragma unroll
        for (int q = 0; q < 4; q++) o[j][q] = 0.f;
    float m0r = -INFINITY, m1r = -INFINITY, l0 = 0.f, l1 = 0.f;

    int qg0 = q0 + 16 * wid + g;
    int qg1 = qg0 + 8;

    const int NT = SEQ / 64;
    for (int c = 0; c < NT; c++) {           // EPS-mask quirk: ALL tiles
        CP_WAIT(1);
        __syncthreads();
        // prefetch stage c+2 into (c+2)%3 FIRST — last read in iter c-1.
        if (c + 2 < NT) {
            int tt = t & 127;
            int dst = (c + 2) % 3;
            #pragma unroll
            for (int u = 0; u < 4; u++) {
                int idx = u * 128 + tt;
                int r = idx >> 3, w = idx & 7;
                const __half* gsrc = base + (size_t)((c + 2) * 64 + r) * (3 * DM) + n * 64 + w * 8;
                if (t < 128)
                    cp_async16(sb + (uint32_t)((KOFFH(dst) + r * KVSTR + w * 8) * 2), gsrc + DM);
                else
                    cp_async16(sb + (uint32_t)((VOFFH(dst) + r * KVSTR + w * 8) * 2), gsrc + 2 * DM);
            }
        }
        CP_COMMIT();

        uint32_t kbase = sb + (uint32_t)(KOFFH(c % 3) * 2);
        uint32_t vbase = sb + (uint32_t)(VOFFH(c % 3) * 2);

        // S = Q K^T : 4 ks x 4 j2, 32 mmas
        float sc[8][4];
        #pragma unroll
        for (int j = 0; j < 8; j++)
            #pragma unroll
            for (int q = 0; q < 4; q++) sc[j][q] = 0.f;
        #pragma unroll
        for (int ks = 0; ks < 4; ks++)
            #pragma unroll
            for (int j2 = 0; j2 < 4; j2++) {
                uint32_t bb[4];
                ldm_x4(bb, kbase + (uint32_t)(((j2 * 16 + b_row) * KVSTR + ks * 16 + b_kof) * 2));
                mma16816(sc[j2 * 2],     qa[ks], bb[0], bb[1]);
                mma16816(sc[j2 * 2 + 1], qa[ks], bb[2], bb[3]);
            }

        // mask + online softmax
        int k0 = c * 64;
        float mt0 = -INFINITY, mt1 = -INFINITY;
        #pragma unroll
        for (int j = 0; j < 8; j++) {
            int kc = k0 + j * 8 + 2 * tig;
            if (qg0 < kc)     sc[j][0] = 1e-10f;
            if (qg0 < kc + 1) sc[j][1] = 1e-10f;
            if (qg1 < kc)     sc[j][2] = 1e-10f;
            if (qg1 < kc + 1) sc[j][3] = 1e-10f;
            mt0 = fmaxf(mt0, fmaxf(sc[j][0], sc[j][1]));
            mt1 = fmaxf(mt1, fmaxf(sc[j][2], sc[j][3]));
        }
        #pragma unroll
        for (int msk = 1; msk < 4; msk <<= 1) {
            mt0 = fmaxf(mt0, __shfl_xor_sync(0xffffffffu, mt0, msk));
            mt1 = fmaxf(mt1, __shfl_xor_sync(0xffffffffu, mt1, msk));
        }
        float mn0 = fmaxf(m0r, mt0), mn1 = fmaxf(m1r, mt1);
        float lt0 = 0.f, lt1 = 0.f;
        #pragma unroll
        for (int j = 0; j < 8; j++) {
            sc[j][0] = __expf(sc[j][0] - mn0);
            sc[j][1] = __expf(sc[j][1] - mn0);
            sc[j][2] = __expf(sc[j][2] - mn1);
            sc[j][3] = __expf(sc[j][3] - mn1);
            lt0 += sc[j][0] + sc[j][1];
            lt1 += sc[j][2] + sc[j][3];
        }
        #pragma unroll
        for (int msk = 1; msk < 4; msk <<= 1) {
            lt0 += __shfl_xor_sync(0xffffffffu, lt0, msk);
            lt1 += __shfl_xor_sync(0xffffffffu, lt1, msk);
        }
        float c0 = __expf(m0r - mn0), c1 = __expf(m1r - mn1);
        l0 = l0 * c0 + lt0;  l1 = l1 * c1 + lt1;
        m0r = mn0;  m1r = mn1;
        #pragma unroll
        for (int j = 0; j < 8; j++) {
            o[j][0] *= c0; o[j][1] *= c0;
            o[j][2] *= c1; o[j][3] *= c1;
        }

        // P -> smem as half2 pairs (stride 36 u32 = 72 halves)
        #pragma unroll
        for (int j = 0; j < 8; j++) {
            __half2 p01 = __floats2half2_rn(sc[j][0], sc[j][1]);
            __half2 p23 = __floats2half2_rn(sc[j][2], sc[j][3]);
            Pu[qr * 36 + j * 4 + tig]       = *reinterpret_cast<uint32_t*>(&p01);
            Pu[(qr + 8) * 36 + j * 4 + tig] = *reinterpret_cast<uint32_t*>(&p23);
        }
        __syncwarp();

        // O += P V : 4 k16-steps; P frags ldmatrix.x4, V^T ldmatrix.x4.trans
        #pragma unroll
        for (int ks = 0; ks < 4; ks++) {
            uint32_t pa[4];
            ldm_x4(pa, sb + (uint32_t)(((16 * wid + a_row) * KVSTR + ks * 16 + a_kof) * 2));
            #pragma unroll
            for (int cb = 0; cb < 4; cb++) {
                int row = ks * 16 + lr + (quad & 1) * 8;
                int col = cb * 16 + (quad >> 1) * 8;
                uint32_t vv[4];
                ldm_x4_trans(vv, vbase + (uint32_t)((row * KVSTR + col) * 2));
                mma16816(o[cb * 2],     pa, vv[0], vv[1]);
                mma16816(o[cb * 2 + 1], pa, vv[2], vv[3]);
            }
        }
    }

    // writeback (half: feeds attn-out GEMM A operand)
    float inv0 = 1.0f / l0, inv1 = 1.0f / l1;
    size_t r0 = (size_t)(b * SEQ + q0 + 16 * wid + g) * DM;
    size_t r1 = r0 + 8 * DM;
    #pragma unroll
    for (int hj = 0; hj < 8; hj++) {
        int col = n * 64 + hj * 8 + 2 * tig;
        *reinterpret_cast<__half2*>(ctx + r0 + col) =
            __floats2half2_rn(o[hj][0] * inv0, o[hj][1] * inv0);
        *reinterpret_cast<__half2*>(ctx + r1 + col) =
            __floats2half2_rn(o[hj][2] * inv1, o[hj][3] * inv1);
    }
}

// ---------------- launch -----------------------------------------------------
extern "C" void kernel_launch(void* const* d_in, const int* in_sizes, int n_in,
                              void* d_out, int out_size)
{
    const float* residual   = (const float*)d_in[0];
    const float* W_key      = (const float*)d_in[1];
    const float* W_query    = (const float*)d_in[2];
    const float* W_values   = (const float*)d_in[3];
    const float* W_attn_out = (const float*)d_in[4];
    const float* B_key      = (const float*)d_in[5];
    const float* B_query    = (const float*)d_in[6];
    const float* B_values   = (const float*)d_in[7];
    const float* B_attn_out = (const float*)d_in[8];
    const float* ln1_w      = (const float*)d_in[9];
    const float* ln1_b      = (const float*)d_in[10];
    const float* ln2_w      = (const float*)d_in[11];
    const float* ln2_b      = (const float*)d_in[12];
    const float* W_mlp_in   = (const float*)d_in[13];
    const float* W_mlp_out  = (const float*)d_in[14];
    const float* B_mlp_in   = (const float*)d_in[15];
    const float* B_mlp_out  = (const float*)d_in[16];
    float* out = (float*)d_out;

    __half *xln, *qkvp, *ctxp, *yp, *hp, *wqkvt, *watt, *wmin, *wmout;
    float *midp, *bqkvp;
    cudaGetSymbolAddress((void**)&xln,   g_xln);
    cudaGetSymbolAddress((void**)&qkvp,  g_qkv);
    cudaGetSymbolAddress((void**)&ctxp,  g_ctx);
    cudaGetSymbolAddress((void**)&midp,  g_mid);
    cudaGetSymbolAddress((void**)&yp,    g_y);
    cudaGetSymbolAddress((void**)&hp,    g_h);
    cudaGetSymbolAddress((void**)&wqkvt, g_wqkv_t);
    cudaGetSymbolAddress((void**)&watt,  g_watt_t);
    cudaGetSymbolAddress((void**)&wmin,  g_wmin_t);
    cudaGetSymbolAddress((void**)&wmout, g_wmout_t);
    cudaGetSymbolAddress((void**)&bqkvp, g_bqkv);

    const int GS = NSTG * GSTGB;   // 81920 B
    cudaFuncSetAttribute(mgemm,     cudaFuncAttributeMaxDynamicSharedMemorySize, GS);
    cudaFuncSetAttribute(flash_mma, cudaFuncAttributeMaxDynamicSharedMemorySize, FLASH_SMEM);

    dim3 t32x8(32, 8);

    // weight prep (deterministic every call)
    qkv_t_kernel<<<dim3(DM / 32, DH / 32, 48), t32x8>>>(W_query, W_key, W_values);
    bias_pack_kernel<<<12, 256>>>(B_query, B_key, B_values);
    transpose3_kernel<<<9216, t32x8>>>(W_attn_out, W_mlp_in, W_mlp_out);

    // 1. LN1
    ln_kernel<<<MROWS, 256>>>(residual, ln1_w, ln1_b, xln);
    // 2. QKV projection [4096,1024]x[1024,3072]
    mgemm<<<dim3(3 * DM / 128, MROWS / 128), 256, GS>>>(
        xln, wqkvt, qkvp, MROWS, 3 * DM, DM, bqkvp, nullptr, 0);
    // 3. attention (EPS-masked full softmax, fp16 tensor cores)
    flash_mma<<<dim3(SEQ / 128, BATCH * NH), 256, FLASH_SMEM>>>(qkvp, ctxp);
    // 4. attn out projection + residual -> mid (fp32)
    mgemm<<<dim3(DM / 128, MROWS / 128), 256, GS>>>(
        ctxp, watt, midp, MROWS, DM, DM, B_attn_out, residual, 2);
    // 5. LN2
    ln_kernel<<<MROWS, 256>>>(midp, ln2_w, ln2_b, yp);
    // 6. MLP in + exact GELU
    mgemm<<<dim3(DMLP / 128, MROWS / 128), 256, GS>>>(
        yp, wmin, hp, MROWS, DMLP, DM, B_mlp_in, nullptr, 1);
    // 7. MLP out + residual -> output (fp32)
    mgemm<<<dim3(DM / 128, MROWS / 128), 256, GS>>>(
        hp, wmout, out, MROWS, DM, DMLP, B_mlp_out, midp, 2);
}

// round 16
// speedup vs baseline: 1.6718x; 1.6718x over previous
#include <cuda_runtime.h>
#include <cuda_fp16.h>
#include <math.h>
#include <stdint.h>

#define MROWS 4096   // B * S
#define DM    1024
#define DH    64
#define NH    16
#define DMLP  4096
#define SEQ   2048
#define BATCH 2

// ---------------- scratch (static device globals; no runtime alloc) ----------
__device__ __half g_xln   [MROWS * DM];
__device__ __half g_qkv   [MROWS * 3 * DM];   // [row][{Q,K,V} x (n*64+h)]
__device__ __half g_ctx   [MROWS * DM];
__device__ float  g_mid   [MROWS * DM];       // fp32: residual carrier
__device__ __half g_y     [MROWS * DM];
__device__ __half g_h     [MROWS * DMLP];
__device__ __half g_wqkv_t[3 * DM * DM];      // [N=3072][K=1024]
__device__ __half g_watt_t[DM * DM];          // [N=1024][K=1024]
__device__ __half g_wmin_t[DMLP * DM];        // [N=4096][K=1024]
__device__ __half g_wmout_t[DM * DMLP];       // [N=1024][K=4096]
__device__ float  g_bqkv  [3 * DM];

// ---------------- helpers ----------------------------------------------------
__device__ __forceinline__ uint32_t smem_u32(const void* p) {
    uint32_t a;
    asm("{ .reg .u64 t; cvta.to.shared.u64 t, %1; cvt.u32.u64 %0, t; }" : "=r"(a) : "l"(p));
    return a;
}
__device__ __forceinline__ void cp_async16(uint32_t s, const void* g) {
    asm volatile("cp.async.cg.shared.global [%0], [%1], 16;" :: "r"(s), "l"(g));
}
#define CP_COMMIT() asm volatile("cp.async.commit_group;")
#define CP_WAIT(n)  asm volatile("cp.async.wait_group %0;" :: "n"(n))

__device__ __forceinline__ void ldm_x4(uint32_t* r, uint32_t addr) {
    asm volatile("ldmatrix.sync.aligned.m8n8.x4.shared.b16 {%0,%1,%2,%3}, [%4];"
        : "=r"(r[0]), "=r"(r[1]), "=r"(r[2]), "=r"(r[3]) : "r"(addr));
}
__device__ __forceinline__ void ldm_x4_trans(uint32_t* r, uint32_t addr) {
    asm volatile("ldmatrix.sync.aligned.m8n8.x4.trans.shared.b16 {%0,%1,%2,%3}, [%4];"
        : "=r"(r[0]), "=r"(r[1]), "=r"(r[2]), "=r"(r[3]) : "r"(addr));
}

// mma.m16n8k16 f16 -> f32
__device__ __forceinline__ void mma16816(float* c, const uint32_t* a,
                                         uint32_t b0, uint32_t b1) {
    asm volatile(
        "mma.sync.aligned.m16n8k16.row.col.f32.f16.f16.f32 "
        "{%0,%1,%2,%3}, {%4,%5,%6,%7}, {%8,%9}, {%0,%1,%2,%3};"
        : "+f"(c[0]), "+f"(c[1]), "+f"(c[2]), "+f"(c[3])
        : "r"(a[0]), "r"(a[1]), "r"(a[2]), "r"(a[3]), "r"(b0), "r"(b1));
}

// ---------------- layernorm: fp32 in -> half out ------------------------------
__global__ __launch_bounds__(256) void ln_kernel(const float* __restrict__ x,
                                                 const float* __restrict__ w,
                                                 const float* __restrict__ bb,
                                                 __half* __restrict__ out)
{
    int row = blockIdx.x;
    int t = threadIdx.x;
    const float* xr = x + (size_t)row * DM;
    float4 xv = reinterpret_cast<const float4*>(xr)[t];
    float s  = xv.x + xv.y + xv.z + xv.w;
    float sq = xv.x*xv.x + xv.y*xv.y + xv.z*xv.z + xv.w*xv.w;
    #pragma unroll
    for (int off = 16; off > 0; off >>= 1) {
        s  += __shfl_xor_sync(0xffffffffu, s,  off);
        sq += __shfl_xor_sync(0xffffffffu, sq, off);
    }
    __shared__ float ss[8], sk[8];
    __shared__ float smean, sinv;
    if ((t & 31) == 0) { ss[t >> 5] = s; sk[t >> 5] = sq; }
    __syncthreads();
    if (t == 0) {
        float S = 0.f, Q = 0.f;
        #pragma unroll
        for (int i = 0; i < 8; i++) { S += ss[i]; Q += sk[i]; }
        float mean = S * (1.0f / DM);
        float var  = Q * (1.0f / DM) - mean * mean;
        smean = mean;
        sinv  = rsqrtf(var + 1e-5f);
    }
    __syncthreads();
    float mean = smean, inv = sinv;
    float4 wv = reinterpret_cast<const float4*>(w)[t];
    float4 bv = reinterpret_cast<const float4*>(bb)[t];
    __half2* o2 = reinterpret_cast<__half2*>(out + (size_t)row * DM);
    o2[2 * t]     = __floats2half2_rn((xv.x - mean) * inv * wv.x + bv.x,
                                      (xv.y - mean) * inv * wv.y + bv.y);
    o2[2 * t + 1] = __floats2half2_rn((xv.z - mean) * inv * wv.z + bv.z,
                                      (xv.w - mean) * inv * wv.w + bv.w);
}

// ---------------- batched weight transposes (to [N][K], half) -----------------
__global__ void transpose3_kernel(const float* __restrict__ Watt,
                                  const float* __restrict__ Wmin,
                                  const float* __restrict__ Wmout)
{
    __shared__ float tile[32][33];
    int bid = blockIdx.x;
    const float* in; __half* out; int R, C, bx, by;
    if (bid < 1024) {                       // W_attn_out [1024][1024]
        in = Watt; out = g_watt_t; R = DM; C = DM;
        bx = bid & 31; by = bid >> 5;
    } else if (bid < 1024 + 4096) {         // W_mlp_in [1024][4096]
        int v = bid - 1024;
        in = Wmin; out = g_wmin_t; R = DM; C = DMLP;
        bx = v & 127; by = v >> 7;
    } else {                                // W_mlp_out [4096][1024]
        int v = bid - 5120;
        in = Wmout; out = g_wmout_t; R = DMLP; C = DM;
        bx = v & 31; by = v >> 5;
    }
    int r0 = by * 32, c0 = bx * 32;
    int tx = threadIdx.x, ty = threadIdx.y;
    #pragma unroll
    for (int i = 0; i < 32; i += 8)
        tile[ty + i][tx] = in[(size_t)(r0 + ty + i) * C + c0 + tx];
    __syncthreads();
    #pragma unroll
    for (int i = 0; i < 32; i += 8)
        out[(size_t)(c0 + ty + i) * R + r0 + tx] = __float2half_rn(tile[tx][ty + i]);
}

// QKV: g_wqkv_t[(sel*1024 + n*64 + h)][e] = W_sel[n][e][h]; query scaled by 1/8
__global__ void qkv_t_kernel(const float* __restrict__ Wq, const float* __restrict__ Wk,
                             const float* __restrict__ Wv)
{
    __shared__ float tile[32][33];
    int b   = blockIdx.z;
    int sel = b >> 4, n = b & 15;
    const float* W = (sel == 0) ? Wq : (sel == 1) ? Wk : Wv;
    float scale = (sel == 0) ? 0.125f : 1.0f;
    const float* src = W + (size_t)n * DM * DH;       // [E=1024][H=64]
    int e0 = blockIdx.x * 32, h0 = blockIdx.y * 32;
    int tx = threadIdx.x, ty = threadIdx.y;
    #pragma unroll
    for (int i = 0; i < 32; i += 8)
        tile[ty + i][tx] = src[(size_t)(e0 + ty + i) * DH + h0 + tx];
    __syncthreads();
    #pragma unroll
    for (int i = 0; i < 32; i += 8)
        g_wqkv_t[(size_t)(sel * DM + n * 64 + h0 + ty + i) * DM + e0 + tx] =
            __float2half_rn(tile[tx][ty + i] * scale);
}

__global__ void bias_pack_kernel(const float* __restrict__ Bq, const float* __restrict__ Bk,
                                 const float* __restrict__ Bv)
{
    int idx = blockIdx.x * 256 + threadIdx.x;
    if (idx < 3 * DM) {
        int sel = idx / DM, col = idx % DM;
        const float* Bp = (sel == 0) ? Bq : (sel == 1) ? Bk : Bv;
        g_bqkv[idx] = Bp[col] * (sel == 0 ? 0.125f : 1.0f);
    }
}

// ---------------- pipelined fp16 mma GEMM: 128x128, 4-stage (R13 exact) --------
// Prefetch AFTER compute (R15 lesson: issuing cp.async before the ldmatrix
// stream makes the fragment loads queue behind LDGSTS in the L1tex FIFO).
// mode 0: +bias -> half   1: +bias,GELU -> half   2: +bias,+add(f32) -> f32
#define GSTGB 20480   // bytes per stage: 256 rows * 40 halves * 2
#define NSTG  4

__global__ __launch_bounds__(256) void mgemm(
    const __half* __restrict__ A, const __half* __restrict__ Bt,
    void* __restrict__ Cv, int M, int N, int K,
    const float* __restrict__ bias, const float* __restrict__ add, int mode)
{
    extern __shared__ __align__(16) unsigned char smb[];
    uint32_t sb = smem_u32(smb);
    int t    = threadIdx.x;
    int lane = t & 31, wid = t >> 5;
    int g    = lane >> 2, tig = lane & 3;
    int lr   = lane & 7, quad = lane >> 3;
    int wm   = (wid >> 1) * 32;
    int wn   = (wid & 1) * 64;
    int m0   = blockIdx.y * 128, n0 = blockIdx.x * 128;
    int NC   = K >> 5;

    float acc[2][8][4];
    #pragma unroll
    for (int i = 0; i < 2; i++)
        #pragma unroll
        for (int j = 0; j < 8; j++)
            #pragma unroll
            for (int q = 0; q < 4; q++) acc[i][j][q] = 0.f;

    // cp.async slots: 4 x 16B (8 halves) per thread per stage
    uint32_t so[4];
    const __half* gp[4];
    #pragma unroll
    for (int u = 0; u < 4; u++) {
        int idx = u * 256 + t;
        bool isB = idx >= 512;
        int v = idx & 511;
        int r = v >> 2, w = v & 3;
        so[u] = (uint32_t)(((isB ? 5120 : 0) + r * 40 + w * 8) * 2);
        gp[u] = (isB ? Bt + (size_t)(n0 + r) * K : A + (size_t)(m0 + r) * K) + w * 8;
    }

    // prologue: stages 0,1,2
    #pragma unroll
    for (int c = 0; c < 3; c++) {
        uint32_t base = sb + c * GSTGB;
        #pragma unroll
        for (int u = 0; u < 4; u++) cp_async16(base + so[u], gp[u] + c * 32);
        CP_COMMIT();
    }

    // per-lane ldmatrix base offsets (halves)
    int a_row = lr + (quad & 1) * 8, a_kof = (quad >> 1) * 8;       // A-type frag
    int b_row = lr + (quad >> 1) * 8, b_kof = (quad & 1) * 8;       // B-type frag

    for (int c = 0; c < NC; c++) {
        CP_WAIT(2);
        __syncthreads();
        uint32_t stb = sb + (c % NSTG) * GSTGB;
        #pragma unroll
        for (int ko = 0; ko < 32; ko += 16) {   // halves
            uint32_t a[2][4];
            #pragma unroll
            for (int i = 0; i < 2; i++)
                ldm_x4(a[i], stb + (uint32_t)(((wm + i * 16 + a_row) * 40 + ko + a_kof) * 2));
            #pragma unroll
            for (int j2 = 0; j2 < 4; j2++) {
                uint32_t bb[4];
                ldm_x4(bb, stb + (uint32_t)(((128 + wn + j2 * 16 + b_row) * 40 + ko + b_kof) * 2));
                mma16816(acc[0][j2 * 2],     a[0], bb[0], bb[1]);
                mma16816(acc[1][j2 * 2],     a[1], bb[0], bb[1]);
                mma16816(acc[0][j2 * 2 + 1], a[0], bb[2], bb[3]);
                mma16816(acc[1][j2 * 2 + 1], a[1], bb[2], bb[3]);
            }
        }
        // prefetch c+3 into (c+3)%4 == (c-1)%4 after compute (R13 order)
        if (c + 3 < NC) {
            uint32_t base = sb + ((c + 3) % NSTG) * GSTGB;
            #pragma unroll
            for (int u = 0; u < 4; u++) cp_async16(base + so[u], gp[u] + (c + 3) * 32);
        }
        CP_COMMIT();
    }

    // epilogue
    #pragma unroll
    for (int i = 0; i < 2; i++) {
        int r0 = m0 + wm + i * 16 + g;
        int r1 = r0 + 8;
        #pragma unroll
        for (int j = 0; j < 8; j++) {
            int col = n0 + wn + j * 8 + 2 * tig;
            float b0 = bias[col], b1 = bias[col + 1];
            float v0 = acc[i][j][0] + b0, v1 = acc[i][j][1] + b1;
            float v2 = acc[i][j][2] + b0, v3 = acc[i][j][3] + b1;
            if (mode == 1) {
                v0 = 0.5f * v0 * (1.0f + erff(v0 * 0.70710678118654752f));
                v1 = 0.5f * v1 * (1.0f + erff(v1 * 0.70710678118654752f));
                v2 = 0.5f * v2 * (1.0f + erff(v2 * 0.70710678118654752f));
                v3 = 0.5f * v3 * (1.0f + erff(v3 * 0.70710678118654752f));
            }
            if (mode == 2) {
                float* C = (float*)Cv;
                float2 a0 = *reinterpret_cast<const float2*>(add + (size_t)r0 * N + col);
                float2 a1 = *reinterpret_cast<const float2*>(add + (size_t)r1 * N + col);
                *reinterpret_cast<float2*>(C + (size_t)r0 * N + col) = make_float2(v0 + a0.x, v1 + a0.y);
                *reinterpret_cast<float2*>(C + (size_t)r1 * N + col) = make_float2(v2 + a1.x, v3 + a1.y);
            } else {
                __half* C = (__half*)Cv;
                *reinterpret_cast<__half2*>(C + (size_t)r0 * N + col) = __floats2half2_rn(v0, v1);
                *reinterpret_cast<__half2*>(C + (size_t)r1 * N + col) = __floats2half2_rn(v2, v3);
            }
        }
    }
}

// ---------------- fp16 flash attention: QT=128, KT=64, 3-stage KV (R13) --------
// Single variable vs R13: __launch_bounds__(256, 2) forces occupancy 2
// (naturally reg-limited to 1; R14/R15 delta showed the bound is a large win).
#define KVSTR 72
#define KOFFH(s) (9216 + (s) * 4608)
#define VOFFH(s) (23040 + (s) * 4608)
#define FLASH_SMEM 73728

__global__ __launch_bounds__(256, 2) void flash_mma(const __half* __restrict__ qkv,
                                                    __half* __restrict__ ctx)
{
    extern __shared__ __align__(16) unsigned char smb[];
    uint32_t sb = smem_u32(smb);
    int t    = threadIdx.x;
    int lane = t & 31, wid = t >> 5;
    int g    = lane >> 2, tig = lane & 3;
    int lr   = lane & 7, quad = lane >> 3;
    int n    = blockIdx.y & (NH - 1);
    int b    = blockIdx.y >> 4;
    int q0   = blockIdx.x * 128;
    const __half* base = qkv + (size_t)b * SEQ * (3 * DM);

    // Q tile: 128 rows x 64 halves = 1024 chunks
    #pragma unroll
    for (int u = 0; u < 4; u++) {
        int idx = u * 256 + t;
        int r = idx >> 3, w = idx & 7;
        cp_async16(sb + (uint32_t)((r * KVSTR + w * 8) * 2),
                   base + (size_t)(q0 + r) * (3 * DM) + n * 64 + w * 8);
    }
    CP_COMMIT();
    // KV stages 0,1: 64 rows x 8 chunks each; t<128 K, t>=128 V
    {
        int tt = t & 127;
        #pragma unroll
        for (int s = 0; s < 2; s++) {
            #pragma unroll
            for (int u = 0; u < 4; u++) {
                int idx = u * 128 + tt;
                int r = idx >> 3, w = idx & 7;
                const __half* gsrc = base + (size_t)(s * 64 + r) * (3 * DM) + n * 64 + w * 8;
                if (t < 128)
                    cp_async16(sb + (uint32_t)((KOFFH(s) + r * KVSTR + w * 8) * 2), gsrc + DM);
                else
                    cp_async16(sb + (uint32_t)((VOFFH(s) + r * KVSTR + w * 8) * 2), gsrc + 2 * DM);
            }
            CP_COMMIT();
        }
    }
    CP_WAIT(2);              // Q group complete
    __syncthreads();

    int a_row = lr + (quad & 1) * 8, a_kof = (quad >> 1) * 8;   // A-type frag
    int b_row = lr + (quad >> 1) * 8, b_kof = (quad & 1) * 8;   // B-type frag

    // preload Q frags; Q region becomes P after
    uint32_t qa[4][4];
    #pragma unroll
    for (int ks = 0; ks < 4; ks++)
        ldm_x4(qa[ks], sb + (uint32_t)(((16 * wid + a_row) * KVSTR + ks * 16 + a_kof) * 2));
    uint32_t* Pu = reinterpret_cast<uint32_t*>(smb);   // overlay, stride 36 u32
    int qr = 16 * wid + g;

    float o[8][4];
    #pragma unroll
    for (int j = 0; j < 8; j++)
        #pragma unroll
        for (int q = 0; q < 4; q++) o[j][q] = 0.f;
    float m0r = -INFINITY, m1r = -INFINITY, l0 = 0.f, l1 = 0.f;

    int qg0 = q0 + 16 * wid + g;
    int qg1 = qg0 + 8;

    const int NT = SEQ / 64;
    for (int c = 0; c < NT; c++) {           // EPS-mask quirk: ALL tiles
        CP_WAIT(1);
        __syncthreads();
        uint32_t kbase = sb + (uint32_t)(KOFFH(c % 3) * 2);
        uint32_t vbase = sb + (uint32_t)(VOFFH(c % 3) * 2);

        // S = Q K^T : 4 ks x 4 j2, 32 mmas
        float sc[8][4];
        #pragma unroll
        for (int j = 0; j < 8; j++)
            #pragma unroll
            for (int q = 0; q < 4; q++) sc[j][q] = 0.f;
        #pragma unroll
        for (int ks = 0; ks < 4; ks++)
            #pragma unroll
            for (int j2 = 0; j2 < 4; j2++) {
                uint32_t bb[4];
                ldm_x4(bb, kbase + (uint32_t)(((j2 * 16 + b_row) * KVSTR + ks * 16 + b_kof) * 2));
                mma16816(sc[j2 * 2],     qa[ks], bb[0], bb[1]);
                mma16816(sc[j2 * 2 + 1], qa[ks], bb[2], bb[3]);
            }

        // mask + online softmax
        int k0 = c * 64;
        float mt0 = -INFINITY, mt1 = -INFINITY;
        #pragma unroll
        for (int j = 0; j < 8; j++) {
            int kc = k0 + j * 8 + 2 * tig;
            if (qg0 < kc)     sc[j][0] = 1e-10f;
            if (qg0 < kc + 1) sc[j][1] = 1e-10f;
            if (qg1 < kc)     sc[j][2] = 1e-10f;
            if (qg1 < kc + 1) sc[j][3] = 1e-10f;
            mt0 = fmaxf(mt0, fmaxf(sc[j][0], sc[j][1]));
            mt1 = fmaxf(mt1, fmaxf(sc[j][2], sc[j][3]));
        }
        #pragma unroll
        for (int msk = 1; msk < 4; msk <<= 1) {
            mt0 = fmaxf(mt0, __shfl_xor_sync(0xffffffffu, mt0, msk));
            mt1 = fmaxf(mt1, __shfl_xor_sync(0xffffffffu, mt1, msk));
        }
        float mn0 = fmaxf(m0r, mt0), mn1 = fmaxf(m1r, mt1);
        float lt0 = 0.f, lt1 = 0.f;
        #pragma unroll
        for (int j = 0; j < 8; j++) {
            sc[j][0] = __expf(sc[j][0] - mn0);
            sc[j][1] = __expf(sc[j][1] - mn0);
            sc[j][2] = __expf(sc[j][2] - mn1);
            sc[j][3] = __expf(sc[j][3] - mn1);
            lt0 += sc[j][0] + sc[j][1];
            lt1 += sc[j][2] + sc[j][3];
        }
        #pragma unroll
        for (int msk = 1; msk < 4; msk <<= 1) {
            lt0 += __shfl_xor_sync(0xffffffffu, lt0, msk);
            lt1 += __shfl_xor_sync(0xffffffffu, lt1, msk);
        }
        float c0 = __expf(m0r - mn0), c1 = __expf(m1r - mn1);
        l0 = l0 * c0 + lt0;  l1 = l1 * c1 + lt1;
        m0r = mn0;  m1r = mn1;
        #pragma unroll
        for (int j = 0; j < 8; j++) {
            o[j][0] *= c0; o[j][1] *= c0;
            o[j][2] *= c1; o[j][3] *= c1;
        }

        // P -> smem as half2 pairs (stride 36 u32 = 72 halves)
        #pragma unroll
        for (int j = 0; j < 8; j++) {
            __half2 p01 = __floats2half2_rn(sc[j][0], sc[j][1]);
            __half2 p23 = __floats2half2_rn(sc[j][2], sc[j][3]);
            Pu[qr * 36 + j * 4 + tig]       = *reinterpret_cast<uint32_t*>(&p01);
            Pu[(qr + 8) * 36 + j * 4 + tig] = *reinterpret_cast<uint32_t*>(&p23);
        }
        __syncwarp();

        // O += P V : 4 k16-steps; P frags ldmatrix.x4, V^T ldmatrix.x4.trans
        #pragma unroll
        for (int ks = 0; ks < 4; ks++) {
            uint32_t pa[4];
            ldm_x4(pa, sb + (uint32_t)(((16 * wid + a_row) * KVSTR + ks * 16 + a_kof) * 2));
            #pragma unroll
            for (int cb = 0; cb < 4; cb++) {
                int row = ks * 16 + lr + (quad & 1) * 8;
                int col = cb * 16 + (quad >> 1) * 8;
                uint32_t vv[4];
                ldm_x4_trans(vv, vbase + (uint32_t)((row * KVSTR + col) * 2));
                mma16816(o[cb * 2],     pa, vv[0], vv[1]);
                mma16816(o[cb * 2 + 1], pa, vv[2], vv[3]);
            }
        }

        // prefetch stage c+2 into (c+2)%3 after compute (R13 order)
        if (c + 2 < NT) {
            int tt = t & 127;
            int dst = (c + 2) % 3;
            #pragma unroll
            for (int u = 0; u < 4; u++) {
                int idx = u * 128 + tt;
                int r = idx >> 3, w = idx & 7;
                const __half* gsrc = base + (size_t)((c + 2) * 64 + r) * (3 * DM) + n * 64 + w * 8;
                if (t < 128)
                    cp_async16(sb + (uint32_t)((KOFFH(dst) + r * KVSTR + w * 8) * 2), gsrc + DM);
                else
                    cp_async16(sb + (uint32_t)((VOFFH(dst) + r * KVSTR + w * 8) * 2), gsrc + 2 * DM);
            }
        }
        CP_COMMIT();
    }

    // writeback (half: feeds attn-out GEMM A operand)
    float inv0 = 1.0f / l0, inv1 = 1.0f / l1;
    size_t r0 = (size_t)(b * SEQ + q0 + 16 * wid + g) * DM;
    size_t r1 = r0 + 8 * DM;
    #pragma unroll
    for (int hj = 0; hj < 8; hj++) {
        int col = n * 64 + hj * 8 + 2 * tig;
        *reinterpret_cast<__half2*>(ctx + r0 + col) =
            __floats2half2_rn(o[hj][0] * inv0, o[hj][1] * inv0);
        *reinterpret_cast<__half2*>(ctx + r1 + col) =
            __floats2half2_rn(o[hj][2] * inv1, o[hj][3] * inv1);
    }
}

// ---------------- launch -----------------------------------------------------
extern "C" void kernel_launch(void* const* d_in, const int* in_sizes, int n_in,
                              void* d_out, int out_size)
{
    const float* residual   = (const float*)d_in[0];
    const float* W_key      = (const float*)d_in[1];
    const float* W_query    = (const float*)d_in[2];
    const float* W_values   = (const float*)d_in[3];
    const float* W_attn_out = (const float*)d_in[4];
    const float* B_key      = (const float*)d_in[5];
    const float* B_query    = (const float*)d_in[6];
    const float* B_values   = (const float*)d_in[7];
    const float* B_attn_out = (const float*)d_in[8];
    const float* ln1_w      = (const float*)d_in[9];
    const float* ln1_b      = (const float*)d_in[10];
    const float* ln2_w      = (const float*)d_in[11];
    const float* ln2_b      = (const float*)d_in[12];
    const float* W_mlp_in   = (const float*)d_in[13];
    const float* W_mlp_out  = (const float*)d_in[14];
    const float* B_mlp_in   = (const float*)d_in[15];
    const float* B_mlp_out  = (const float*)d_in[16];
    float* out = (float*)d_out;

    __half *xln, *qkvp, *ctxp, *yp, *hp, *wqkvt, *watt, *wmin, *wmout;
    float *midp, *bqkvp;
    cudaGetSymbolAddress((void**)&xln,   g_xln);
    cudaGetSymbolAddress((void**)&qkvp,  g_qkv);
    cudaGetSymbolAddress((void**)&ctxp,  g_ctx);
    cudaGetSymbolAddress((void**)&midp,  g_mid);
    cudaGetSymbolAddress((void**)&yp,    g_y);
    cudaGetSymbolAddress((void**)&hp,    g_h);
    cudaGetSymbolAddress((void**)&wqkvt, g_wqkv_t);
    cudaGetSymbolAddress((void**)&watt,  g_watt_t);
    cudaGetSymbolAddress((void**)&wmin,  g_wmin_t);
    cudaGetSymbolAddress((void**)&wmout, g_wmout_t);
    cudaGetSymbolAddress((void**)&bqkvp, g_bqkv);

    const int GS = NSTG * GSTGB;   // 81920 B
    cudaFuncSetAttribute(mgemm,     cudaFuncAttributeMaxDynamicSharedMemorySize, GS);
    cudaFuncSetAttribute(flash_mma, cudaFuncAttributeMaxDynamicSharedMemorySize, FLASH_SMEM);

    dim3 t32x8(32, 8);

    // weight prep (deterministic every call)
    qkv_t_kernel<<<dim3(DM / 32, DH / 32, 48), t32x8>>>(W_query, W_key, W_values);
    bias_pack_kernel<<<12, 256>>>(B_query, B_key, B_values);
    transpose3_kernel<<<9216, t32x8>>>(W_attn_out, W_mlp_in, W_mlp_out);

    // 1. LN1
    ln_kernel<<<MROWS, 256>>>(residual, ln1_w, ln1_b, xln);
    // 2. QKV projection [4096,1024]x[1024,3072]
    mgemm<<<dim3(3 * DM / 128, MROWS / 128), 256, GS>>>(
        xln, wqkvt, qkvp, MROWS, 3 * DM, DM, bqkvp, nullptr, 0);
    // 3. attention (EPS-masked full softmax, fp16 tensor cores)
    flash_mma<<<dim3(SEQ / 128, BATCH * NH), 256, FLASH_SMEM>>>(qkvp, ctxp);
    // 4. attn out projection + residual -> mid (fp32)
    mgemm<<<dim3(DM / 128, MROWS / 128), 256, GS>>>(
        ctxp, watt, midp, MROWS, DM, DM, B_attn_out, residual, 2);
    // 5. LN2
    ln_kernel<<<MROWS, 256>>>(midp, ln2_w, ln2_b, yp);
    // 6. MLP in + exact GELU
    mgemm<<<dim3(DMLP / 128, MROWS / 128), 256, GS>>>(
        yp, wmin, hp, MROWS, DMLP, DM, B_mlp_in, nullptr, 1);
    // 7. MLP out + residual -> output (fp32)
    mgemm<<<dim3(DM / 128, MROWS / 128), 256, GS>>>(
        hp, wmout, out, MROWS, DM, DMLP, B_mlp_out, midp, 2);
}